// round 4
// baseline (speedup 1.0000x reference)
#include <cuda_runtime.h>
#include <cstdint>

#define BB 4
#define NN 1024
#define DD 768
#define HH 12
#define HD 64
#define BH 48
#define KTH 104857

typedef unsigned long long ull;

// ---------------- scratch ----------------
__device__ float g_qkv[4096 * 2304];
__device__ float g_attn[(size_t)48 * 1024 * 1024];
__device__ float g_ao[4096 * 768];
__device__ unsigned g_hist[48 * 2048];
__device__ unsigned g_sel[48];
__device__ int g_krem[48];
__device__ float g_thr[48];
__device__ unsigned g_cand[(size_t)48 * 1048576];
__device__ int g_ccnt[48];

__device__ __forceinline__ unsigned fkey(float f) {
    unsigned u = __float_as_uint(f);
    return (u & 0x80000000u) ? ~u : (u ^ 0x80000000u);
}

// ---------------- packed f32x2 helpers ----------------
__device__ __forceinline__ void ffma2(ull& acc, ull a, ull b) {
    asm("fma.rn.f32x2 %0, %1, %2, %0;" : "+l"(acc) : "l"(a), "l"(b));
}
__device__ __forceinline__ ull pack2(float x, float y) {
    ull r;
    asm("mov.b64 %0, {%1, %2};" : "=l"(r) : "f"(x), "f"(y));
    return r;
}
__device__ __forceinline__ float2 unpack2(ull v) {
    float2 r;
    asm("mov.b64 {%0, %1}, %2;" : "=f"(r.x), "=f"(r.y) : "l"(v));
    return r;
}

// ---------------------------------------------------------------------------
// Generic GEMM: C[M,N] = A[M,K] @ B[K,N] + bias[N]
// 128x128 tile, BK=8, 256 threads, 8x8 per thread, FFMA2 inner product.
// ---------------------------------------------------------------------------
__global__ void __launch_bounds__(256) gemm128_bias(
    const float* __restrict__ A, const float* __restrict__ Bm,
    const float* __restrict__ bias, float* __restrict__ C,
    int M, int Nn, int K) {
    __shared__ float As[8][128];
    __shared__ float Bs[8][128];
    int t = threadIdx.x;
    int n0 = blockIdx.x * 128;
    int m0 = blockIdx.y * 128;
    int tx = t & 15, ty = t >> 4;
    ull acc[8][4];
#pragma unroll
    for (int i = 0; i < 8; i++)
#pragma unroll
        for (int j = 0; j < 4; j++) acc[i][j] = 0ULL;

    int arow = t >> 1, acol = (t & 1) * 4;
    int brow = t >> 5, bcol = (t & 31) * 4;

    for (int k0 = 0; k0 < K; k0 += 8) {
        float4 av = *(const float4*)(A + (size_t)(m0 + arow) * K + k0 + acol);
        As[acol + 0][arow] = av.x;
        As[acol + 1][arow] = av.y;
        As[acol + 2][arow] = av.z;
        As[acol + 3][arow] = av.w;
        float4 bv = *(const float4*)(Bm + (size_t)(k0 + brow) * Nn + n0 + bcol);
        *(float4*)&Bs[brow][bcol] = bv;
        __syncthreads();
#pragma unroll
        for (int kk = 0; kk < 8; kk++) {
            ull aa[8], b2[4];
            const ull* bp = (const ull*)&Bs[kk][tx * 8];
#pragma unroll
            for (int j = 0; j < 4; j++) b2[j] = bp[j];
#pragma unroll
            for (int i = 0; i < 8; i++) {
                float a = As[kk][ty * 8 + i];
                aa[i] = pack2(a, a);
            }
#pragma unroll
            for (int i = 0; i < 8; i++)
#pragma unroll
                for (int j = 0; j < 4; j++) ffma2(acc[i][j], aa[i], b2[j]);
        }
        __syncthreads();
    }
    float bb[8];
#pragma unroll
    for (int j = 0; j < 8; j++) bb[j] = bias[n0 + tx * 8 + j];
#pragma unroll
    for (int i = 0; i < 8; i++) {
        int row = m0 + ty * 8 + i;
#pragma unroll
        for (int j0 = 0; j0 < 2; j0++) {
            float2 p0 = unpack2(acc[i][j0 * 2 + 0]);
            float2 p1 = unpack2(acc[i][j0 * 2 + 1]);
            float4 v;
            v.x = p0.x + bb[j0 * 4 + 0];
            v.y = p0.y + bb[j0 * 4 + 1];
            v.z = p1.x + bb[j0 * 4 + 2];
            v.w = p1.y + bb[j0 * 4 + 3];
            *(float4*)(C + (size_t)row * Nn + n0 + tx * 8 + j0 * 4) = v;
        }
    }
}

// ---------------------------------------------------------------------------
// Scores: S[bh][n][m] = 0.125 * sum_d Q[n,d] K[m,d]  (+ fused pass-0 hist)
// ---------------------------------------------------------------------------
__global__ void __launch_bounds__(256) gemm_scores() {
    __shared__ float Qs[8][128];
    __shared__ float Ks[8][128];
    __shared__ unsigned hsm[2048];
    int bh = blockIdx.z;
    int b = bh / HH, h = bh % HH;
    const float* Q = g_qkv + (size_t)b * NN * 2304 + h * HD;
    const float* Kp = g_qkv + (size_t)b * NN * 2304 + 768 + h * HD;
    float* S = g_attn + (size_t)bh * NN * NN;

    int t = threadIdx.x;
    int m0 = blockIdx.x * 128;   // key index
    int n0 = blockIdx.y * 128;   // query index
    int tx = t & 15, ty = t >> 4;
    for (int j = t; j < 2048; j += 256) hsm[j] = 0u;
    ull acc[8][4];
#pragma unroll
    for (int i = 0; i < 8; i++)
#pragma unroll
        for (int j = 0; j < 4; j++) acc[i][j] = 0ULL;

    int r = t >> 1, c4 = (t & 1) * 4;

    for (int d0 = 0; d0 < HD; d0 += 8) {
        float4 qv = *(const float4*)(Q + (size_t)(n0 + r) * 2304 + d0 + c4);
        Qs[c4 + 0][r] = qv.x; Qs[c4 + 1][r] = qv.y;
        Qs[c4 + 2][r] = qv.z; Qs[c4 + 3][r] = qv.w;
        float4 kv = *(const float4*)(Kp + (size_t)(m0 + r) * 2304 + d0 + c4);
        Ks[c4 + 0][r] = kv.x; Ks[c4 + 1][r] = kv.y;
        Ks[c4 + 2][r] = kv.z; Ks[c4 + 3][r] = kv.w;
        __syncthreads();
#pragma unroll
        for (int kk = 0; kk < 8; kk++) {
            ull aa[8], b2[4];
            const ull* bp = (const ull*)&Ks[kk][tx * 8];
#pragma unroll
            for (int j = 0; j < 4; j++) b2[j] = bp[j];
#pragma unroll
            for (int i = 0; i < 8; i++) {
                float a = Qs[kk][ty * 8 + i];
                aa[i] = pack2(a, a);
            }
#pragma unroll
            for (int i = 0; i < 8; i++)
#pragma unroll
                for (int j = 0; j < 4; j++) ffma2(acc[i][j], aa[i], b2[j]);
        }
        __syncthreads();
    }
#pragma unroll
    for (int i = 0; i < 8; i++) {
        int row = n0 + ty * 8 + i;
#pragma unroll
        for (int j0 = 0; j0 < 2; j0++) {
            float2 p0 = unpack2(acc[i][j0 * 2 + 0]);
            float2 p1 = unpack2(acc[i][j0 * 2 + 1]);
            float4 v;
            v.x = p0.x * 0.125f;
            v.y = p0.y * 0.125f;
            v.z = p1.x * 0.125f;
            v.w = p1.y * 0.125f;
            atomicAdd(&hsm[fkey(v.x) >> 21], 1u);
            atomicAdd(&hsm[fkey(v.y) >> 21], 1u);
            atomicAdd(&hsm[fkey(v.z) >> 21], 1u);
            atomicAdd(&hsm[fkey(v.w) >> 21], 1u);
            *(float4*)(S + (size_t)row * NN + m0 + tx * 8 + j0 * 4) = v;
        }
    }
    __syncthreads();
    unsigned* gh = g_hist + bh * 2048;
    for (int j = t; j < 2048; j += 256) {
        unsigned c = hsm[j];
        if (c) atomicAdd(&gh[j], c);
    }
}

// ---------------------------------------------------------------------------
// Selection: scan -> candidate gather -> final select over candidates
// ---------------------------------------------------------------------------
__global__ void sel_init() {
    int bh = blockIdx.x, t = threadIdx.x;
    for (int j = t; j < 2048; j += 256) g_hist[bh * 2048 + j] = 0u;
    if (t == 0) g_ccnt[bh] = 0;
}

__global__ void scan0() {
    int bh = blockIdx.x, t = threadIdx.x;
    __shared__ unsigned ssum[256];
    __shared__ int s_sel;
    __shared__ unsigned s_kin;
    const unsigned* hist = g_hist + bh * 2048;
    unsigned loc[8], lsum = 0;
#pragma unroll
    for (int i = 0; i < 8; i++) { loc[i] = hist[t * 8 + i]; lsum += loc[i]; }
    ssum[t] = lsum;
    __syncthreads();
    if (t == 0) {
        unsigned k = KTH, cum = 0, kin = k;
        int sel = 255;
        for (int i = 0; i < 256; i++) {
            if (cum + ssum[i] >= k) { sel = i; kin = k - cum; break; }
            cum += ssum[i];
        }
        s_sel = sel; s_kin = kin;
    }
    __syncthreads();
    if (t == s_sel) {
        unsigned kk = s_kin, cum = 0, d = t * 8 + 7, knew = kk;
#pragma unroll
        for (int i = 0; i < 8; i++) {
            if (cum + loc[i] >= kk) { d = t * 8 + i; knew = kk - cum; break; }
            cum += loc[i];
        }
        g_sel[bh] = d;
        g_krem[bh] = (int)knew;
    }
}

__device__ __forceinline__ void push_cand(unsigned key, unsigned sel, unsigned* cand,
                                          int* cnt, unsigned lane) {
    bool m = (key >> 21) == sel;
    unsigned bal = __ballot_sync(0xffffffffu, m);
    if (bal) {
        int leader = __ffs(bal) - 1;
        int base = 0;
        if ((int)lane == leader) base = atomicAdd(cnt, __popc(bal));
        base = __shfl_sync(0xffffffffu, base, leader);
        if (m) cand[base + __popc(bal & ((1u << lane) - 1u))] = key;
    }
}

__global__ void cand_pass() {
    int bh = blockIdx.y, t = threadIdx.x;
    unsigned lane = t & 31;
    unsigned sel = g_sel[bh];
    unsigned* cand = g_cand + (size_t)bh * 1048576;
    int* cnt = &g_ccnt[bh];
    const float4* Sp = (const float4*)(g_attn + (size_t)bh * 1048576) +
                       (size_t)blockIdx.x * 8192;
    for (int i = 0; i < 32; i++) {
        float4 v = Sp[i * 256 + t];
        push_cand(fkey(v.x), sel, cand, cnt, lane);
        push_cand(fkey(v.y), sel, cand, cnt, lane);
        push_cand(fkey(v.z), sel, cand, cnt, lane);
        push_cand(fkey(v.w), sel, cand, cnt, lane);
    }
}

__global__ void sel_final() {
    int bh = blockIdx.x, t = threadIdx.x;
    __shared__ unsigned sh[2048];
    __shared__ unsigned ssum[256];
    __shared__ int s_sel;
    __shared__ unsigned s_kin;
    __shared__ unsigned s_b1, s_k2;
    int cnt = g_ccnt[bh];
    const unsigned* cand = g_cand + (size_t)bh * 1048576;

    // pass A: bits 20..10
    for (int j = t; j < 2048; j += 256) sh[j] = 0u;
    __syncthreads();
    for (int i = t; i < cnt; i += 256) atomicAdd(&sh[(cand[i] >> 10) & 2047u], 1u);
    __syncthreads();
    {
        unsigned loc[8], lsum = 0;
#pragma unroll
        for (int i = 0; i < 8; i++) { loc[i] = sh[t * 8 + i]; lsum += loc[i]; }
        ssum[t] = lsum;
        __syncthreads();
        if (t == 0) {
            unsigned k = (unsigned)g_krem[bh], cum = 0, kin = k;
            int sel = 255;
            for (int i = 0; i < 256; i++) {
                if (cum + ssum[i] >= k) { sel = i; kin = k - cum; break; }
                cum += ssum[i];
            }
            s_sel = sel; s_kin = kin;
        }
        __syncthreads();
        if (t == s_sel) {
            unsigned kk = s_kin, cum = 0, d = t * 8 + 7, knew = kk;
#pragma unroll
            for (int i = 0; i < 8; i++) {
                if (cum + loc[i] >= kk) { d = t * 8 + i; knew = kk - cum; break; }
                cum += loc[i];
            }
            s_b1 = d; s_k2 = knew;
        }
        __syncthreads();
    }
    unsigned b1 = s_b1;
    __syncthreads();

    // pass B: bits 9..0
    for (int j = t; j < 1024; j += 256) sh[j] = 0u;
    __syncthreads();
    for (int i = t; i < cnt; i += 256) {
        unsigned ky = cand[i];
        if (((ky >> 10) & 2047u) == b1) atomicAdd(&sh[ky & 1023u], 1u);
    }
    __syncthreads();
    {
        unsigned loc[4], lsum = 0;
#pragma unroll
        for (int i = 0; i < 4; i++) { loc[i] = sh[t * 4 + i]; lsum += loc[i]; }
        ssum[t] = lsum;
        __syncthreads();
        if (t == 0) {
            unsigned k = s_k2, cum = 0, kin = k;
            int sel = 255;
            for (int i = 0; i < 256; i++) {
                if (cum + ssum[i] >= k) { sel = i; kin = k - cum; break; }
                cum += ssum[i];
            }
            s_sel = sel; s_kin = kin;
        }
        __syncthreads();
        if (t == s_sel) {
            unsigned kk = s_kin, cum = 0, d = t * 4 + 3;
#pragma unroll
            for (int i = 0; i < 4; i++) {
                if (cum + loc[i] >= kk) { d = t * 4 + i; break; }
                cum += loc[i];
            }
            unsigned key = (g_sel[bh] << 21) | (b1 << 10) | d;
            unsigned bits = (key & 0x80000000u) ? (key ^ 0x80000000u) : ~key;
            g_thr[bh] = __uint_as_float(bits);
        }
    }
}

// ---------------------------------------------------------------------------
// Masked softmax (float4, one block per row, in place)
// ---------------------------------------------------------------------------
__global__ void softmax_mask() {
    int row = blockIdx.x, bh = row >> 10;
    float thr = g_thr[bh];
    float4* S = (float4*)(g_attn + (size_t)row * NN);
    int t = threadIdx.x;
    unsigned lane = t & 31, w = t >> 5;
    __shared__ float red[8];

    float4 vv = S[t];
    float v[4] = {vv.x, vv.y, vv.z, vv.w};
    bool keep[4];
    float mx = -3.0e38f;
#pragma unroll
    for (int i = 0; i < 4; i++) {
        keep[i] = v[i] > thr;
        if (keep[i]) mx = fmaxf(mx, v[i]);
    }
#pragma unroll
    for (int o = 16; o; o >>= 1) mx = fmaxf(mx, __shfl_xor_sync(0xffffffffu, mx, o));
    if (lane == 0) red[w] = mx;
    __syncthreads();
    float m = red[0];
#pragma unroll
    for (int i = 1; i < 8; i++) m = fmaxf(m, red[i]);

    float e[4], s = 0.f;
#pragma unroll
    for (int i = 0; i < 4; i++) {
        e[i] = keep[i] ? __expf(v[i] - m) : 0.f;
        s += e[i];
    }
#pragma unroll
    for (int o = 16; o; o >>= 1) s += __shfl_xor_sync(0xffffffffu, s, o);
    __syncthreads();
    if (lane == 0) red[w] = s;
    __syncthreads();
    float tot = 0.f;
#pragma unroll
    for (int i = 0; i < 8; i++) tot += red[i];
    float inv = 1.f / tot;
    float4 ov = {e[0] * inv, e[1] * inv, e[2] * inv, e[3] * inv};
    S[t] = ov;
}

// ---------------------------------------------------------------------------
// AV: O[b,n,h*64+j] = sum_m P[bh][n][m] V[b,m,h,j];  128x64x8 tile, FFMA2
// ---------------------------------------------------------------------------
__global__ void __launch_bounds__(256) gemm_av() {
    int bh = blockIdx.z;
    int b = bh / HH, h = bh % HH;
    const float* P = g_attn + (size_t)bh * NN * NN;
    const float* V = g_qkv + (size_t)b * NN * 2304 + 1536 + h * HD;
    float* O = g_ao + (size_t)b * NN * DD + h * HD;

    __shared__ float As[8][128];
    __shared__ float Bs[8][64];
    int t = threadIdx.x;
    int m0 = blockIdx.y * 128;
    int tx = t & 15, ty = t >> 4;
    ull acc[8][2];
#pragma unroll
    for (int i = 0; i < 8; i++)
#pragma unroll
        for (int j = 0; j < 2; j++) acc[i][j] = 0ULL;

    int arow = t >> 1, acol = (t & 1) * 4;

    for (int k0 = 0; k0 < NN; k0 += 8) {
        float4 av = *(const float4*)(P + (size_t)(m0 + arow) * NN + k0 + acol);
        As[acol + 0][arow] = av.x;
        As[acol + 1][arow] = av.y;
        As[acol + 2][arow] = av.z;
        As[acol + 3][arow] = av.w;
        if (t < 128) {
            int brow = t >> 4, bcol = (t & 15) * 4;
            float4 bv = *(const float4*)(V + (size_t)(k0 + brow) * 2304 + bcol);
            *(float4*)&Bs[brow][bcol] = bv;
        }
        __syncthreads();
#pragma unroll
        for (int kk = 0; kk < 8; kk++) {
            ull aa[8], b2[2];
            const ull* bp = (const ull*)&Bs[kk][tx * 4];
            b2[0] = bp[0]; b2[1] = bp[1];
#pragma unroll
            for (int i = 0; i < 8; i++) {
                float a = As[kk][ty * 8 + i];
                aa[i] = pack2(a, a);
            }
#pragma unroll
            for (int i = 0; i < 8; i++)
#pragma unroll
                for (int j = 0; j < 2; j++) ffma2(acc[i][j], aa[i], b2[j]);
        }
        __syncthreads();
    }
#pragma unroll
    for (int i = 0; i < 8; i++) {
        int row = m0 + ty * 8 + i;
        float2 p0 = unpack2(acc[i][0]);
        float2 p1 = unpack2(acc[i][1]);
        float4 v = {p0.x, p0.y, p1.x, p1.y};
        *(float4*)(O + (size_t)row * DD + tx * 4) = v;
    }
}

// ---------------------------------------------------------------------------
extern "C" void kernel_launch(void* const* d_in, const int* in_sizes, int n_in,
                              void* d_out, int out_size) {
    const float* x = (const float*)d_in[0];
    const float* W_qkv = (const float*)d_in[1];
    const float* b_qkv = (const float*)d_in[2];
    const float* W_out = (const float*)d_in[3];
    const float* b_out = (const float*)d_in[4];
    float* out = (float*)d_out;

    float* qkv_p; cudaGetSymbolAddress((void**)&qkv_p, g_qkv);
    float* ao_p;  cudaGetSymbolAddress((void**)&ao_p, g_ao);

    // 0. zero hist + cand counters
    sel_init<<<BH, 256>>>();
    // 1. QKV projection: [4096,768] @ [768,2304] + bias
    gemm128_bias<<<dim3(2304 / 128, 4096 / 128), 256>>>(x, W_qkv, b_qkv, qkv_p,
                                                        4096, 2304, 768);
    // 2. Scores (+ fused pass-0 histogram)
    gemm_scores<<<dim3(8, 8, BH), 256>>>();
    // 3. Threshold (exact kth smallest)
    scan0<<<BH, 256>>>();
    cand_pass<<<dim3(32, BH), 256>>>();
    sel_final<<<BH, 256>>>();
    // 4. Masked softmax in place
    softmax_mask<<<BH * NN, 256>>>();
    // 5. P @ V
    gemm_av<<<dim3(1, 8, BH), 256>>>();
    // 6. Output projection: [4096,768] @ [768,768] + bias
    gemm128_bias<<<dim3(768 / 128, 4096 / 128), 256>>>(ao_p, W_out, b_out, out,
                                                       4096, 768, 768);
}